// round 15
// baseline (speedup 1.0000x reference)
#include <cuda_runtime.h>
#include <math.h>

// Problem constants
#define BB 4096
#define KK 64
#define FF 128
#define TE 32
#define DD 160
#define NT 10000
#define INV_SQRT_D 0.07905694150420949f   // 1/sqrt(160)
#define FULL 0xffffffffu

// ---------------- scratch (__device__ globals) ----------------------------------
__device__ __align__(16) float g_tbl[NT * TE];   // cos(t*w+b) table
__device__ __align__(16) float g_Mt[DD * DD];    // Mt[g][o] = (Wk^T Wq / sqrt(D))[o][g]
__device__ __align__(16) float g_Pt[DD * DD];    // Pt[g][e] = (out_w @ Wv)[e][g]
__device__ float g_m0[DD];
__device__ float g_w0[DD];
__device__ float g_p0[DD];
__device__ float g_b00[1];
__device__ __align__(16) float g_U[BB * DD];     // transformed queries
__device__ float g_S0[BB];                       // score bias
__device__ __align__(16) float g_Acc[BB * DD];   // attn-weighted kv accumulation

// ---------------- kernel 0: fold weights + cos table (merged) --------------------
#define PREP_BLKS (2 * DD + 1)
__global__ void __launch_bounds__(256)
setup_kernel(const float* __restrict__ ipw,
             const float* __restrict__ ipb,
             const float* __restrict__ outw,
             const float* __restrict__ outb,
             const float* __restrict__ tw,
             const float* __restrict__ tb) {
    int bidx = blockIdx.x;
    int t = threadIdx.x;
    if (bidx < PREP_BLKS) {
        if (t >= DD) return;
        if (bidx < DD) {
            int f = bidx;
            float acc = 0.f;
            for (int d = 0; d < DD; ++d)
                acc = fmaf(ipw[(DD + d) * DD + f], ipw[d * DD + t], acc);
            g_Mt[t * DD + f] = acc * INV_SQRT_D;           // transposed
        } else if (bidx < 2 * DD) {
            int e = bidx - DD;
            float acc = 0.f;
            for (int d = 0; d < DD; ++d)
                acc = fmaf(outw[e * DD + d], ipw[(2 * DD + d) * DD + t], acc);
            g_Pt[t * DD + e] = acc;                        // transposed
        } else {
            float m0 = 0.f, w0 = 0.f, p0 = 0.f;
            for (int d = 0; d < DD; ++d) {
                m0 = fmaf(ipw[(DD + d) * DD + t], ipb[d], m0);
                w0 = fmaf(ipw[d * DD + t], ipb[DD + d], w0);
                p0 = fmaf(outw[t * DD + d], ipb[2 * DD + d], p0);
            }
            g_m0[t] = m0 * INV_SQRT_D;
            g_w0[t] = w0 * INV_SQRT_D;
            g_p0[t] = p0 + outb[t];
            if (t == 0) {
                float b00 = 0.f;
                for (int d = 0; d < DD; ++d) b00 = fmaf(ipb[d], ipb[DD + d], b00);
                g_b00[0] = b00 * INV_SQRT_D;
            }
        }
    } else {
        int idx = (bidx - PREP_BLKS) * 256 + t;
        if (idx >= NT * TE) return;
        int tt = idx >> 5;
        int j = idx & 31;
        float arg = __fadd_rn(__fmul_rn((float)tt, tw[j]), tb[j]);
        float kf = rintf(arg * 0.15915494309189535f);
        double r = fma(-(double)kf, 6.283185307179586, (double)arg);
        g_tbl[idx] = cosf((float)r);
    }
}

// ---------------- fused GEMM: 8b x 160o tile, 512 blocks x 256 thr ---------------
// warp w owns output row b0+w (tile 1x5 per thread).
// PH0: A = gather(x, tbl) by target ids; C = g_U; side-product S0.
// PH1: A = g_Acc; C = out1 (attn_out); fused mlp-dot + leaky edge weights.
template <int PH>
__global__ void __launch_bounds__(256)
gemm_kernel(const float* __restrict__ x,
            const int* __restrict__ tgt_ids,
            const int* __restrict__ tgt_times,
            const float* __restrict__ ew,
            const float* __restrict__ mlpw,
            const float* __restrict__ mlpb,
            float* __restrict__ out1,
            float* __restrict__ out2) {
    __shared__ float As[2][8][16];
    __shared__ float Bs[2][16][DD];
    __shared__ float sw0[DD];
    __shared__ int   stg[8], stt[8];
    __shared__ float smlp[DD + 2];

    const float* Bt   = (PH == 0) ? g_Mt : g_Pt;
    const float* bias = (PH == 0) ? g_m0 : g_p0;

    int t = threadIdx.x;
    int lane = t & 31, w = t >> 5;       // warp 0..7 = row
    int b0 = blockIdx.x * 8;

    if (PH == 0) {
        if (t < DD) sw0[t] = g_w0[t];
        if (t < 8) { stg[t] = tgt_ids[b0 + t]; stt[t] = tgt_times[b0 + t]; }
    } else {
        if (t < DD + 1) smlp[t] = mlpw[t];
        if (t == 0) smlp[DD + 1] = mlpb[0];
    }
    __syncthreads();

    // A-chunk loaders: threads 0..127, one float each (8 rows x 16 g)
    int ar = t >> 4, ac = t & 15;
    int tg = 0, ttm = 0;
    if (PH == 0 && t < 128) { tg = stg[ar]; ttm = stt[ar]; }

    // B-chunk cooperative load (16x160 = 640 float4): t, t+256, t+512(<128)
    int i1 = t + 256, i2 = t + 512;
    int b0r = t / 40,  b0c = (t % 40) * 4;
    int b1r = i1 / 40, b1c = (i1 % 40) * 4;
    int b2r = i2 / 40, b2c = (i2 % 40) * 4;

    float acc[5] = {0.f, 0.f, 0.f, 0.f, 0.f};
    float s0p = 0.f;

    float va = 0.f;
    float4 pb0, pb1, pb2;

    // prologue chunk 0
    if (t < 128) {
        if (PH == 0)
            va = (ac < FF) ? x[tg * FF + ac] : g_tbl[ttm * TE + (ac - FF)];
        else
            va = g_Acc[(b0 + ar) * DD + ac];
        if (PH == 0) s0p = va * sw0[ac];
    }
    pb0 = *(const float4*)&Bt[b0r * DD + b0c];
    pb1 = *(const float4*)&Bt[b1r * DD + b1c];
    if (t < 128) pb2 = *(const float4*)&Bt[b2r * DD + b2c];
    if (t < 128) As[0][ar][ac] = va;
    *(float4*)&Bs[0][b0r][b0c] = pb0;
    *(float4*)&Bs[0][b1r][b1c] = pb1;
    if (t < 128) *(float4*)&Bs[0][b2r][b2c] = pb2;

    for (int c = 0; c < 10; ++c) {
        __syncthreads();
        int cur = c & 1;
        if (c < 9) {
            int g0 = (c + 1) * 16;
            if (t < 128) {
                int g = g0 + ac;
                if (PH == 0)
                    va = (g < FF) ? x[tg * FF + g] : g_tbl[ttm * TE + (g - FF)];
                else
                    va = g_Acc[(b0 + ar) * DD + g];
                if (PH == 0) s0p = fmaf(va, sw0[g], s0p);
            }
            pb0 = *(const float4*)&Bt[(g0 + b0r) * DD + b0c];
            pb1 = *(const float4*)&Bt[(g0 + b1r) * DD + b1c];
            if (t < 128) pb2 = *(const float4*)&Bt[(g0 + b2r) * DD + b2c];
        }
#pragma unroll
        for (int g = 0; g < 16; ++g) {
            float av = As[cur][w][g];
#pragma unroll
            for (int j = 0; j < 5; ++j)
                acc[j] = fmaf(av, Bs[cur][g][lane + 32 * j], acc[j]);
        }
        if (c < 9) {
            int nb = 1 - cur;
            if (t < 128) As[nb][ar][ac] = va;
            *(float4*)&Bs[nb][b0r][b0c] = pb0;
            *(float4*)&Bs[nb][b1r][b1c] = pb1;
            if (t < 128) *(float4*)&Bs[nb][b2r][b2c] = pb2;
        }
    }

    float bi[5];
#pragma unroll
    for (int j = 0; j < 5; ++j) bi[j] = bias[lane + 32 * j];

    if (PH == 0) {
#pragma unroll
        for (int j = 0; j < 5; ++j)
            g_U[(b0 + w) * DD + lane + 32 * j] = acc[j] + bi[j];
        // S0: reduce over the 16 loader threads of each row
        if (t < 128) {
#pragma unroll
            for (int off = 8; off; off >>= 1)
                s0p += __shfl_down_sync(FULL, s0p, off, 16);
            if (ac == 0) g_S0[b0 + ar] = s0p + g_b00[0];
        }
    } else {
        // warp owns complete row b0+w: bias, store, mlp dot, leaky edges
        float md = 0.f;
        float cb[5];
#pragma unroll
        for (int j = 0; j < 5; ++j) {
            cb[j] = acc[j] + bi[j];
            out1[(b0 + w) * DD + lane + 32 * j] = cb[j];
            md = fmaf(cb[j], smlp[lane + 32 * j], md);
        }
#pragma unroll
        for (int o = 16; o; o >>= 1) md += __shfl_xor_sync(FULL, md, o);
        float wE = smlp[DD], bE = smlp[DD + 1];
        int row = b0 + w;
#pragma unroll
        for (int q = 0; q < 2; ++q) {
            int k = lane + 32 * q;
            float v = md + fmaf(ew[row * KK + k], wE, bE);
            out2[row * KK + k] = (v >= 0.f) ? v : 0.01f * v;
        }
    }
}

// ---------------- phase2: warp-per-target SINGLE-PASS max-free softmax -----------
__global__ void __launch_bounds__(256)
phase2_kernel(const float* __restrict__ x,
              const int* __restrict__ nbr_ids,
              const int* __restrict__ etime,
              const float* __restrict__ gum,
              float* __restrict__ out_mask) {
    int t = threadIdx.x, w = t >> 5, lane = t & 31;
    int b = blockIdx.x * 8 + w;

    const float4* xv = (const float4*)x;
    const float4* tv = (const float4*)g_tbl;
    const float4* uv = (const float4*)g_U;

    int ids0 = nbr_ids[b * KK + lane];
    int ids1 = nbr_ids[b * KK + 32 + lane];
    int ets0 = etime[b * KK + lane];
    int ets1 = etime[b * KK + 32 + lane];
    float gu0 = gum[b * KK + lane];
    float gu1 = gum[b * KK + 32 + lane];

    float4 u4 = uv[b * 40 + lane];
    float4 ut4 = make_float4(0.f, 0.f, 0.f, 0.f);
    if (lane < 8) ut4 = uv[b * 40 + 32 + lane];
    float s0 = g_S0[b];

    float sc0 = 0.f, sc1 = 0.f;            // stashed raw scores (owner lanes)
    float4 ax = make_float4(0.f, 0.f, 0.f, 0.f);
    float4 at = make_float4(0.f, 0.f, 0.f, 0.f);

#pragma unroll
    for (int j = 0; j < 16; ++j) {
        int kk = (4 * j) & 31;
        int idreg = (j < 8) ? ids0 : ids1;
        int etreg = (j < 8) ? ets0 : ets1;
        int nid[4], etv[4];
#pragma unroll
        for (int i = 0; i < 4; ++i) {
            nid[i] = __shfl_sync(FULL, idreg, kk + i);
            etv[i] = __shfl_sync(FULL, etreg, kk + i);
        }
        float4 xr[4], tr[4];
#pragma unroll
        for (int i = 0; i < 4; ++i) xr[i] = xv[nid[i] * 32 + lane];
#pragma unroll
        for (int i = 0; i < 4; ++i)
            tr[i] = (lane < 8) ? tv[etv[i] * 8 + lane] : make_float4(0.f, 0.f, 0.f, 0.f);

        float p[4];
#pragma unroll
        for (int i = 0; i < 4; ++i)
            p[i] = u4.x * xr[i].x + u4.y * xr[i].y + u4.z * xr[i].z + u4.w * xr[i].w
                 + ut4.x * tr[i].x + ut4.y * tr[i].y + ut4.z * tr[i].z + ut4.w * tr[i].w;

        p[0] += __shfl_xor_sync(FULL, p[0], 1);
        p[1] += __shfl_xor_sync(FULL, p[1], 1);
        p[2] += __shfl_xor_sync(FULL, p[2], 1);
        p[3] += __shfl_xor_sync(FULL, p[3], 1);
        float ra = (lane & 1) ? p[1] : p[0];
        float rb = (lane & 1) ? p[3] : p[2];
#pragma unroll
        for (int o = 2; o <= 16; o <<= 1) {
            ra += __shfl_xor_sync(FULL, ra, o);
            rb += __shfl_xor_sync(FULL, rb, o);
        }
        // owner lanes kk..kk+3 hold their own full sums; stash score, compute exp
        int rel = lane - kk;
        float myscore = ((rel == 0 || rel == 1) ? ra : rb) + s0;   // valid on owners
        if (rel >= 0 && rel < 4) {
            if (j < 8) sc0 = myscore; else sc1 = myscore;
        }
        float eo = expf(myscore);          // garbage on non-owners (unused)
        float e[4];
        e[0] = __shfl_sync(FULL, eo, kk);
        e[1] = __shfl_sync(FULL, eo, kk + 1);
        e[2] = __shfl_sync(FULL, eo, kk + 2);
        e[3] = __shfl_sync(FULL, eo, kk + 3);
#pragma unroll
        for (int i = 0; i < 4; ++i) {
            ax.x = fmaf(e[i], xr[i].x, ax.x);
            ax.y = fmaf(e[i], xr[i].y, ax.y);
            ax.z = fmaf(e[i], xr[i].z, ax.z);
            ax.w = fmaf(e[i], xr[i].w, ax.w);
            at.x = fmaf(e[i], tr[i].x, at.x);
            at.y = fmaf(e[i], tr[i].y, at.y);
            at.z = fmaf(e[i], tr[i].z, at.z);
            at.w = fmaf(e[i], tr[i].w, at.w);
        }
    }

    // normalization: sum of exp from stashed scores (bit-identical recompute)
    float e0 = expf(sc0), e1 = expf(sc1);
    float s = e0 + e1;
#pragma unroll
    for (int o = 16; o; o >>= 1) s += __shfl_xor_sync(FULL, s, o);
    float inv = 1.f / s;

    float4 o4;
    o4.x = ax.x * inv; o4.y = ax.y * inv; o4.z = ax.z * inv; o4.w = ax.w * inv;
    ((float4*)&g_Acc[b * DD])[lane] = o4;
    if (lane < 8) {
        float4 o8;
        o8.x = at.x * inv; o8.y = at.y * inv; o8.z = at.z * inv; o8.w = at.w * inv;
        ((float4*)&g_Acc[b * DD])[32 + lane] = o8;
    }

    // gumbel mask (attn weights = e/sum, same values as reference softmax)
    float aw0 = e0 * inv, aw1 = e1 * inv;
    float g0 = -logf(-logf(gu0 + 1e-10f) + 1e-10f);
    float g1 = -logf(-logf(gu1 + 1e-10f) + 1e-10f);
    float z0 = aw0 + g0, z1 = aw1 + g1;
    float zm = fmaxf(z0, z1);
#pragma unroll
    for (int o = 16; o; o >>= 1) zm = fmaxf(zm, __shfl_xor_sync(FULL, zm, o));
    float ez0 = expf(z0 - zm), ez1 = expf(z1 - zm);
    float zs = ez0 + ez1;
#pragma unroll
    for (int o = 16; o; o >>= 1) zs += __shfl_xor_sync(FULL, zs, o);
    out_mask[b * KK + lane]      = (ez0 / zs > 0.2f) ? 1.0f : 0.0f;
    out_mask[b * KK + 32 + lane] = (ez1 / zs > 0.2f) ? 1.0f : 0.0f;
}

// ---------------- launch ----------------------------------------------------------
extern "C" void kernel_launch(void* const* d_in, const int* in_sizes, int n_in,
                              void* d_out, int out_size) {
    const float* x    = (const float*)d_in[0];
    const int*   tgt  = (const int*)  d_in[1];
    const int*   tt   = (const int*)  d_in[2];
    const int*   nbr  = (const int*)  d_in[3];
    const int*   et   = (const int*)  d_in[4];
    const float* ew   = (const float*)d_in[5];
    const float* gu   = (const float*)d_in[6];
    const float* tew  = (const float*)d_in[7];
    const float* teb  = (const float*)d_in[8];
    const float* ipw  = (const float*)d_in[9];
    const float* ipb  = (const float*)d_in[10];
    const float* outw = (const float*)d_in[11];
    const float* outb = (const float*)d_in[12];
    const float* mlpw = (const float*)d_in[13];
    const float* mlpb = (const float*)d_in[14];

    float* o1 = (float*)d_out;           // attn_output     [B, D]
    float* o2 = o1 + BB * DD;            // new_edge_weight [B, K]
    float* o3 = o2 + BB * KK;            // candidate_mask  [B, K]

    int tbl_blks = (NT * TE + 255) / 256;
    setup_kernel<<<PREP_BLKS + tbl_blks, 256>>>(ipw, ipb, outw, outb, tew, teb);
    // gemm<0>: fused gather + Qin@M^T + S0  -> g_U, g_S0  (8 rows/block)
    gemm_kernel<0><<<512, 256>>>(x, tgt, tt, nullptr, nullptr, nullptr, nullptr, nullptr);
    phase2_kernel<<<BB / 8, 256>>>(x, nbr, et, gu, o3);
    // gemm<1>: Acc@P^T + p0 -> attn_out, fused mlp + leaky edge weights
    gemm_kernel<1><<<512, 256>>>(nullptr, nullptr, nullptr, ew, mlpw, mlpb, o1, o2);
}

// round 16
// speedup vs baseline: 1.1899x; 1.1899x over previous
#include <cuda_runtime.h>
#include <math.h>

// Problem constants
#define BB 4096
#define KK 64
#define FF 128
#define TE 32
#define DD 160
#define NT 10000
#define INV_SQRT_D 0.07905694150420949f   // 1/sqrt(160)
#define FULL 0xffffffffu

// ---------------- scratch (__device__ globals) ----------------------------------
__device__ __align__(16) float g_tbl[NT * TE];   // cos(t*w+b) table
__device__ __align__(16) float g_Mt[DD * DD];    // Mt[g][o] = (Wk^T Wq / sqrt(D))[o][g]
__device__ __align__(16) float g_Pt[DD * DD];    // Pt[g][e] = (out_w @ Wv)[e][g]
__device__ float g_m0[DD];
__device__ float g_w0[DD];
__device__ float g_p0[DD];
__device__ float g_b00[1];
__device__ __align__(16) float g_U[BB * DD];     // transformed queries
__device__ float g_S0[BB];                       // score bias
__device__ __align__(16) float g_Acc[BB * DD];   // attn-weighted kv accumulation

// ---------------- kernel 0: fold weights + cos table (merged) --------------------
#define PREP_BLKS (2 * DD + 1)
__global__ void __launch_bounds__(256)
setup_kernel(const float* __restrict__ ipw,
             const float* __restrict__ ipb,
             const float* __restrict__ outw,
             const float* __restrict__ outb,
             const float* __restrict__ tw,
             const float* __restrict__ tb) {
    int bidx = blockIdx.x;
    int t = threadIdx.x;
    if (bidx < PREP_BLKS) {
        if (t >= DD) return;
        if (bidx < DD) {
            int f = bidx;
            float acc = 0.f;
            for (int d = 0; d < DD; ++d)
                acc = fmaf(ipw[(DD + d) * DD + f], ipw[d * DD + t], acc);
            g_Mt[t * DD + f] = acc * INV_SQRT_D;           // transposed
        } else if (bidx < 2 * DD) {
            int e = bidx - DD;
            float acc = 0.f;
            for (int d = 0; d < DD; ++d)
                acc = fmaf(outw[e * DD + d], ipw[(2 * DD + d) * DD + t], acc);
            g_Pt[t * DD + e] = acc;                        // transposed
        } else {
            float m0 = 0.f, w0 = 0.f, p0 = 0.f;
            for (int d = 0; d < DD; ++d) {
                m0 = fmaf(ipw[(DD + d) * DD + t], ipb[d], m0);
                w0 = fmaf(ipw[d * DD + t], ipb[DD + d], w0);
                p0 = fmaf(outw[t * DD + d], ipb[2 * DD + d], p0);
            }
            g_m0[t] = m0 * INV_SQRT_D;
            g_w0[t] = w0 * INV_SQRT_D;
            g_p0[t] = p0 + outb[t];
            if (t == 0) {
                float b00 = 0.f;
                for (int d = 0; d < DD; ++d) b00 = fmaf(ipb[d], ipb[DD + d], b00);
                g_b00[0] = b00 * INV_SQRT_D;
            }
        }
    } else {
        int idx = (bidx - PREP_BLKS) * 256 + t;
        if (idx >= NT * TE) return;
        int tt = idx >> 5;
        int j = idx & 31;
        float arg = __fadd_rn(__fmul_rn((float)tt, tw[j]), tb[j]);
        float kf = rintf(arg * 0.15915494309189535f);
        double r = fma(-(double)kf, 6.283185307179586, (double)arg);
        g_tbl[idx] = cosf((float)r);
    }
}

// ---------------- GEMM: full-B-in-smem, A-in-registers, barrier-free mainloop ----
// grid 256 x 256 thr, 16 rows/block; warp w owns rows b0+2w, b0+2w+1.
// Thread owns cols [4*lane..4*lane+3] and 128+lane.
// PH0: A = gather(x, tbl); C = g_U; side-product S0.
// PH1: A = g_Acc; C = out1; fused mlp-dot + leaky edge weights.
template <int PH>
__global__ void __launch_bounds__(256)
gemm_kernel(const float* __restrict__ x,
            const int* __restrict__ tgt_ids,
            const int* __restrict__ tgt_times,
            const float* __restrict__ ew,
            const float* __restrict__ mlpw,
            const float* __restrict__ mlpb,
            float* __restrict__ out1,
            float* __restrict__ out2) {
    extern __shared__ __align__(16) float sB[];    // 160x160 = 100KB

    const float* Bt   = (PH == 0) ? g_Mt : g_Pt;
    const float* bias = (PH == 0) ? g_m0 : g_p0;

    int t = threadIdx.x;
    int lane = t & 31, w = t >> 5;       // warp 0..7
    int b0 = blockIdx.x * 16;
    int r0 = b0 + 2 * w, r1 = r0 + 1;

    // ---- cooperative B load (once): 6400 float4 / 256 threads = 25 each ----
    {
        const float4* Bv = (const float4*)Bt;
        float4* sBv = (float4*)sB;
#pragma unroll
        for (int i = 0; i < 25; ++i)
            sBv[t + 256 * i] = Bv[t + 256 * i];
    }

    // ---- A rows into registers (overlaps with B load; no dependency) ----
    float a0[5], a1[5];
    if (PH == 0) {
        int tg0 = tgt_ids[r0], tt0 = tgt_times[r0];
        int tg1 = tgt_ids[r1], tt1 = tgt_times[r1];
#pragma unroll
        for (int m = 0; m < 4; ++m) {
            a0[m] = x[tg0 * FF + 32 * m + lane];
            a1[m] = x[tg1 * FF + 32 * m + lane];
        }
        a0[4] = g_tbl[tt0 * TE + lane];
        a1[4] = g_tbl[tt1 * TE + lane];
        // S0 side-product
        float s0p0 = 0.f, s0p1 = 0.f;
#pragma unroll
        for (int m = 0; m < 5; ++m) {
            float wv = g_w0[32 * m + lane];
            s0p0 = fmaf(a0[m], wv, s0p0);
            s0p1 = fmaf(a1[m], wv, s0p1);
        }
        s0p0 += __shfl_xor_sync(FULL, s0p0, 1);
        s0p1 += __shfl_xor_sync(FULL, s0p1, 1);
        float ra = (lane & 1) ? s0p1 : s0p0;
#pragma unroll
        for (int o = 2; o <= 16; o <<= 1) ra += __shfl_xor_sync(FULL, ra, o);
        if (lane < 2) g_S0[r0 + lane] = ra + g_b00[0];
    } else {
#pragma unroll
        for (int m = 0; m < 5; ++m) {
            a0[m] = g_Acc[r0 * DD + 32 * m + lane];
            a1[m] = g_Acc[r1 * DD + 32 * m + lane];
        }
    }

    __syncthreads();   // the only barrier: B resident

    // ---- barrier-free mainloop: 160 g-steps ----
    float acc0[5] = {0.f, 0.f, 0.f, 0.f, 0.f};
    float acc1[5] = {0.f, 0.f, 0.f, 0.f, 0.f};
#pragma unroll
    for (int m = 0; m < 5; ++m) {
#pragma unroll 8
        for (int g2 = 0; g2 < 32; ++g2) {
            float av0 = __shfl_sync(FULL, a0[m], g2);
            float av1 = __shfl_sync(FULL, a1[m], g2);
            int g = 32 * m + g2;
            float4 bv = *(const float4*)&sB[g * DD + 4 * lane];
            float bvx = sB[g * DD + 128 + lane];
            acc0[0] = fmaf(av0, bv.x, acc0[0]);
            acc0[1] = fmaf(av0, bv.y, acc0[1]);
            acc0[2] = fmaf(av0, bv.z, acc0[2]);
            acc0[3] = fmaf(av0, bv.w, acc0[3]);
            acc0[4] = fmaf(av0, bvx,  acc0[4]);
            acc1[0] = fmaf(av1, bv.x, acc1[0]);
            acc1[1] = fmaf(av1, bv.y, acc1[1]);
            acc1[2] = fmaf(av1, bv.z, acc1[2]);
            acc1[3] = fmaf(av1, bv.w, acc1[3]);
            acc1[4] = fmaf(av1, bvx,  acc1[4]);
        }
    }

    float4 bi4 = *(const float4*)&bias[4 * lane];
    float bi1 = bias[128 + lane];

    if (PH == 0) {
        float4 o0 = make_float4(acc0[0] + bi4.x, acc0[1] + bi4.y,
                                acc0[2] + bi4.z, acc0[3] + bi4.w);
        float4 o1 = make_float4(acc1[0] + bi4.x, acc1[1] + bi4.y,
                                acc1[2] + bi4.z, acc1[3] + bi4.w);
        *(float4*)&g_U[r0 * DD + 4 * lane] = o0;
        *(float4*)&g_U[r1 * DD + 4 * lane] = o1;
        g_U[r0 * DD + 128 + lane] = acc0[4] + bi1;
        g_U[r1 * DD + 128 + lane] = acc1[4] + bi1;
    } else {
        float4 mw4 = *(const float4*)&mlpw[4 * lane];
        float mw1 = mlpw[128 + lane];
        float cb0[5], cb1[5];
        cb0[0] = acc0[0] + bi4.x; cb0[1] = acc0[1] + bi4.y;
        cb0[2] = acc0[2] + bi4.z; cb0[3] = acc0[3] + bi4.w;
        cb0[4] = acc0[4] + bi1;
        cb1[0] = acc1[0] + bi4.x; cb1[1] = acc1[1] + bi4.y;
        cb1[2] = acc1[2] + bi4.z; cb1[3] = acc1[3] + bi4.w;
        cb1[4] = acc1[4] + bi1;
        *(float4*)&out1[r0 * DD + 4 * lane] = make_float4(cb0[0], cb0[1], cb0[2], cb0[3]);
        *(float4*)&out1[r1 * DD + 4 * lane] = make_float4(cb1[0], cb1[1], cb1[2], cb1[3]);
        out1[r0 * DD + 128 + lane] = cb0[4];
        out1[r1 * DD + 128 + lane] = cb1[4];
        // mlp dot per row (warp covers all 160 cols)
        float md0 = cb0[0] * mw4.x + cb0[1] * mw4.y + cb0[2] * mw4.z
                  + cb0[3] * mw4.w + cb0[4] * mw1;
        float md1 = cb1[0] * mw4.x + cb1[1] * mw4.y + cb1[2] * mw4.z
                  + cb1[3] * mw4.w + cb1[4] * mw1;
        md0 += __shfl_xor_sync(FULL, md0, 1);
        md1 += __shfl_xor_sync(FULL, md1, 1);
        float ra = (lane & 1) ? md1 : md0;
#pragma unroll
        for (int o = 2; o <= 16; o <<= 1) ra += __shfl_xor_sync(FULL, ra, o);
        float m0 = __shfl_sync(FULL, ra, 0);   // row r0
        float m1 = __shfl_sync(FULL, ra, 1);   // row r1
        float wE = mlpw[DD], bE = mlpb[0];
#pragma unroll
        for (int q = 0; q < 2; ++q) {
            int k = lane + 32 * q;
            float v0 = m0 + fmaf(ew[r0 * KK + k], wE, bE);
            float v1 = m1 + fmaf(ew[r1 * KK + k], wE, bE);
            out2[r0 * KK + k] = (v0 >= 0.f) ? v0 : 0.01f * v0;
            out2[r1 * KK + k] = (v1 >= 0.f) ? v1 : 0.01f * v1;
        }
    }
}

// ---------------- phase2: warp-per-target SINGLE-PASS max-free softmax -----------
__global__ void __launch_bounds__(256)
phase2_kernel(const float* __restrict__ x,
              const int* __restrict__ nbr_ids,
              const int* __restrict__ etime,
              const float* __restrict__ gum,
              float* __restrict__ out_mask) {
    int t = threadIdx.x, w = t >> 5, lane = t & 31;
    int b = blockIdx.x * 8 + w;

    const float4* xv = (const float4*)x;
    const float4* tv = (const float4*)g_tbl;
    const float4* uv = (const float4*)g_U;

    int ids0 = nbr_ids[b * KK + lane];
    int ids1 = nbr_ids[b * KK + 32 + lane];
    int ets0 = etime[b * KK + lane];
    int ets1 = etime[b * KK + 32 + lane];
    float gu0 = gum[b * KK + lane];
    float gu1 = gum[b * KK + 32 + lane];

    float4 u4 = uv[b * 40 + lane];
    float4 ut4 = make_float4(0.f, 0.f, 0.f, 0.f);
    if (lane < 8) ut4 = uv[b * 40 + 32 + lane];
    float s0 = g_S0[b];

    float sc0 = 0.f, sc1 = 0.f;            // stashed raw scores (owner lanes)
    float4 ax = make_float4(0.f, 0.f, 0.f, 0.f);
    float4 at = make_float4(0.f, 0.f, 0.f, 0.f);

#pragma unroll
    for (int j = 0; j < 16; ++j) {
        int kk = (4 * j) & 31;
        int idreg = (j < 8) ? ids0 : ids1;
        int etreg = (j < 8) ? ets0 : ets1;
        int nid[4], etv[4];
#pragma unroll
        for (int i = 0; i < 4; ++i) {
            nid[i] = __shfl_sync(FULL, idreg, kk + i);
            etv[i] = __shfl_sync(FULL, etreg, kk + i);
        }
        float4 xr[4], tr[4];
#pragma unroll
        for (int i = 0; i < 4; ++i) xr[i] = xv[nid[i] * 32 + lane];
#pragma unroll
        for (int i = 0; i < 4; ++i)
            tr[i] = (lane < 8) ? tv[etv[i] * 8 + lane] : make_float4(0.f, 0.f, 0.f, 0.f);

        float p[4];
#pragma unroll
        for (int i = 0; i < 4; ++i)
            p[i] = u4.x * xr[i].x + u4.y * xr[i].y + u4.z * xr[i].z + u4.w * xr[i].w
                 + ut4.x * tr[i].x + ut4.y * tr[i].y + ut4.z * tr[i].z + ut4.w * tr[i].w;

        p[0] += __shfl_xor_sync(FULL, p[0], 1);
        p[1] += __shfl_xor_sync(FULL, p[1], 1);
        p[2] += __shfl_xor_sync(FULL, p[2], 1);
        p[3] += __shfl_xor_sync(FULL, p[3], 1);
        float ra = (lane & 1) ? p[1] : p[0];
        float rb = (lane & 1) ? p[3] : p[2];
#pragma unroll
        for (int o = 2; o <= 16; o <<= 1) {
            ra += __shfl_xor_sync(FULL, ra, o);
            rb += __shfl_xor_sync(FULL, rb, o);
        }
        // owner lanes kk..kk+3 hold their own full sums; stash score, compute exp
        int rel = lane - kk;
        float myscore = ((rel == 0 || rel == 1) ? ra : rb) + s0;   // valid on owners
        if (rel >= 0 && rel < 4) {
            if (j < 8) sc0 = myscore; else sc1 = myscore;
        }
        float eo = expf(myscore);          // garbage on non-owners (unused)
        float e[4];
        e[0] = __shfl_sync(FULL, eo, kk);
        e[1] = __shfl_sync(FULL, eo, kk + 1);
        e[2] = __shfl_sync(FULL, eo, kk + 2);
        e[3] = __shfl_sync(FULL, eo, kk + 3);
#pragma unroll
        for (int i = 0; i < 4; ++i) {
            ax.x = fmaf(e[i], xr[i].x, ax.x);
            ax.y = fmaf(e[i], xr[i].y, ax.y);
            ax.z = fmaf(e[i], xr[i].z, ax.z);
            ax.w = fmaf(e[i], xr[i].w, ax.w);
            at.x = fmaf(e[i], tr[i].x, at.x);
            at.y = fmaf(e[i], tr[i].y, at.y);
            at.z = fmaf(e[i], tr[i].z, at.z);
            at.w = fmaf(e[i], tr[i].w, at.w);
        }
    }

    // normalization: sum of exp from stashed scores (bit-identical recompute)
    float e0 = expf(sc0), e1 = expf(sc1);
    float s = e0 + e1;
#pragma unroll
    for (int o = 16; o; o >>= 1) s += __shfl_xor_sync(FULL, s, o);
    float inv = 1.f / s;

    float4 o4;
    o4.x = ax.x * inv; o4.y = ax.y * inv; o4.z = ax.z * inv; o4.w = ax.w * inv;
    ((float4*)&g_Acc[b * DD])[lane] = o4;
    if (lane < 8) {
        float4 o8;
        o8.x = at.x * inv; o8.y = at.y * inv; o8.z = at.z * inv; o8.w = at.w * inv;
        ((float4*)&g_Acc[b * DD])[32 + lane] = o8;
    }

    // gumbel mask (attn weights = e/sum, same values as reference softmax)
    float aw0 = e0 * inv, aw1 = e1 * inv;
    float g0 = -logf(-logf(gu0 + 1e-10f) + 1e-10f);
    float g1 = -logf(-logf(gu1 + 1e-10f) + 1e-10f);
    float z0 = aw0 + g0, z1 = aw1 + g1;
    float zm = fmaxf(z0, z1);
#pragma unroll
    for (int o = 16; o; o >>= 1) zm = fmaxf(zm, __shfl_xor_sync(FULL, zm, o));
    float ez0 = expf(z0 - zm), ez1 = expf(z1 - zm);
    float zs = ez0 + ez1;
#pragma unroll
    for (int o = 16; o; o >>= 1) zs += __shfl_xor_sync(FULL, zs, o);
    out_mask[b * KK + lane]      = (ez0 / zs > 0.2f) ? 1.0f : 0.0f;
    out_mask[b * KK + 32 + lane] = (ez1 / zs > 0.2f) ? 1.0f : 0.0f;
}

// ---------------- launch ----------------------------------------------------------
extern "C" void kernel_launch(void* const* d_in, const int* in_sizes, int n_in,
                              void* d_out, int out_size) {
    const float* x    = (const float*)d_in[0];
    const int*   tgt  = (const int*)  d_in[1];
    const int*   tt   = (const int*)  d_in[2];
    const int*   nbr  = (const int*)  d_in[3];
    const int*   et   = (const int*)  d_in[4];
    const float* ew   = (const float*)d_in[5];
    const float* gu   = (const float*)d_in[6];
    const float* tew  = (const float*)d_in[7];
    const float* teb  = (const float*)d_in[8];
    const float* ipw  = (const float*)d_in[9];
    const float* ipb  = (const float*)d_in[10];
    const float* outw = (const float*)d_in[11];
    const float* outb = (const float*)d_in[12];
    const float* mlpw = (const float*)d_in[13];
    const float* mlpb = (const float*)d_in[14];

    float* o1 = (float*)d_out;           // attn_output     [B, D]
    float* o2 = o1 + BB * DD;            // new_edge_weight [B, K]
    float* o3 = o2 + BB * KK;            // candidate_mask  [B, K]

    const int smemB = DD * DD * sizeof(float);   // 100KB
    cudaFuncSetAttribute(gemm_kernel<0>, cudaFuncAttributeMaxDynamicSharedMemorySize, smemB);
    cudaFuncSetAttribute(gemm_kernel<1>, cudaFuncAttributeMaxDynamicSharedMemorySize, smemB);

    int tbl_blks = (NT * TE + 255) / 256;
    setup_kernel<<<PREP_BLKS + tbl_blks, 256>>>(ipw, ipb, outw, outb, tew, teb);
    // gemm<0>: fused gather + Qin@M^T + S0  -> g_U, g_S0
    gemm_kernel<0><<<256, 256, smemB>>>(x, tgt, tt, nullptr, nullptr, nullptr, nullptr, nullptr);
    phase2_kernel<<<BB / 8, 256>>>(x, nbr, et, gu, o3);
    // gemm<1>: Acc@P^T + p0 -> attn_out, fused mlp + leaky edge weights
    gemm_kernel<1><<<256, 256, smemB>>>(nullptr, nullptr, nullptr, ew, mlpw, mlpb, o1, o2);
}